// round 9
// baseline (speedup 1.0000x reference)
#include <cuda_runtime.h>

#define B_   32
#define S_   1024
#define ATT_ 512
#define W_   8
#define MONO_S_ 384   // mono energy precomputed for s < MONO_S_
#define MONO_TILES_ 12

// ---------------- scratch (no allocations allowed) ----------------
__device__ float g_qbm[B_ * ATT_];   // dec_h @ Wm^T + bm
__device__ float g_qbc[B_ * ATT_];   // dec_h @ Wc^T + bc
__device__ float g_vnm[ATT_];        // gm * vm / ||vm||
__device__ float g_vnc[ATT_];
__device__ float g_me[B_ * S_];      // monotonic energy
__device__ float g_ce[B_ * S_];      // chunk energy
__device__ float g_beta[B_ * S_];
__device__ int   g_cut[B_];          // per-batch active cutoff (inclusive)

__device__ __forceinline__ float tanha(float x) {
    float y;
    asm("tanh.approx.f32 %0, %1;" : "=f"(y) : "f"(x));
    return y;
}

// ---------------- K0: matvec + vnorm + zero (fused pre-pass) ------
__global__ void __launch_bounds__(256) k_pre(
        const float* __restrict__ dec,
        const float* __restrict__ Wm, const float* __restrict__ bm,
        const float* __restrict__ Wc, const float* __restrict__ bc,
        const float* __restrict__ vm, const float* __restrict__ gm,
        const float* __restrict__ vc, const float* __restrict__ gc,
        float* __restrict__ out) {
    int t = threadIdx.x;

    if (blockIdx.y == 2) {
        int x = blockIdx.x;
        out[x * 512 + t] = 0.f;
        out[x * 512 + 256 + t] = 0.f;
        if (x > 1) return;
        const float* v = x ? vc : vm;
        const float* g = x ? gc : gm;
        float* o       = x ? g_vnc : g_vnm;
        float x1 = v[t], x2 = v[t + 256];
        float ss = x1 * x1 + x2 * x2;
        __shared__ float red[8];
        #pragma unroll
        for (int off = 16; off; off >>= 1) ss += __shfl_down_sync(0xffffffffu, ss, off);
        if ((t & 31) == 0) red[t >> 5] = ss;
        __syncthreads();
        __shared__ float s_scale;
        if (t == 0) {
            float a = red[0] + red[1] + red[2] + red[3] + red[4] + red[5] + red[6] + red[7];
            s_scale = __ldg(g) / sqrtf(a);
        }
        __syncthreads();
        o[t] = x1 * s_scale;
        o[t + 256] = x2 * s_scale;
        return;
    }

    const float* W    = blockIdx.y ? Wc : Wm;
    const float* bias = blockIdx.y ? bc : bm;
    float* qout       = blockIdx.y ? g_qbc : g_qbm;

    int w = t >> 5, lane = t & 31;
    int row0 = blockIdx.x * 16 + w * 2;          // 2 rows per warp

    const float4* W40 = reinterpret_cast<const float4*>(W + (size_t)row0 * 512);
    const float4* W41 = reinterpret_cast<const float4*>(W + (size_t)(row0 + 1) * 512);
    float4 w0[4], w1[4];
    #pragma unroll
    for (int j = 0; j < 4; j++) { w0[j] = W40[lane + 32 * j]; w1[j] = W41[lane + 32 * j]; }
    float bias0 = bias[row0], bias1 = bias[row0 + 1];

    __shared__ float4 sdec[16 * 128];            // 32 KB: 16 batches
    const float4* dec4 = reinterpret_cast<const float4*>(dec);

    #pragma unroll
    for (int half = 0; half < 2; half++) {
        #pragma unroll
        for (int i = t; i < 2048; i += 256) sdec[i] = dec4[half * 2048 + i];
        __syncthreads();
        #pragma unroll 4
        for (int bb = 0; bb < 16; bb++) {
            int b = half * 16 + bb;
            float a0 = 0.f, a1 = 0.f;
            #pragma unroll
            for (int j = 0; j < 4; j++) {
                float4 dv = sdec[bb * 128 + lane + 32 * j];
                a0 += w0[j].x * dv.x + w0[j].y * dv.y + w0[j].z * dv.z + w0[j].w * dv.w;
                a1 += w1[j].x * dv.x + w1[j].y * dv.y + w1[j].z * dv.z + w1[j].w * dv.w;
            }
            #pragma unroll
            for (int off = 16; off; off >>= 1) {
                a0 += __shfl_down_sync(0xffffffffu, a0, off);
                a1 += __shfl_down_sync(0xffffffffu, a1, off);
            }
            if (lane == 0) {
                qout[b * ATT_ + row0]     = a0 + bias0;
                qout[b * ATT_ + row0 + 1] = a1 + bias1;
            }
        }
        __syncthreads();
    }
}

// ---------------- K1: mono energy for s < MONO_S_ ------------------
__global__ void __launch_bounds__(256) k_mono(
        const float* __restrict__ key,
        const float* __restrict__ vbm, const float* __restrict__ rm) {
    int b = blockIdx.y, tile = blockIdx.x;       // tile 0..11
    int t = threadIdx.x, w = t >> 5, lane = t & 31;

    __shared__ float sq[1024];   // [qm 512 | vm 512]
    {
        const float4* qm4 = reinterpret_cast<const float4*>(g_qbm + b * ATT_);
        const float4* vm4 = reinterpret_cast<const float4*>(g_vnm);
        float4* s4 = reinterpret_cast<float4*>(sq);
        if (t < 128) s4[t] = qm4[t];
        else         s4[t] = vm4[t - 128];
    }
    __syncthreads();

    float qm[16], vmr[16];
    #pragma unroll
    for (int j = 0; j < 16; j++) {
        qm[j]  = sq[lane + 32 * j];
        vmr[j] = sq[512 + lane + 32 * j];
    }
    const float cm = __ldg(vbm) + __ldg(rm);

    int s0 = tile * 32 + w * 4;
    #pragma unroll
    for (int r = 0; r < 4; r++) {
        int s = s0 + r;
        const float* kp = key + (((size_t)b * S_ + s) << 9);
        float kv[16];
        #pragma unroll
        for (int j = 0; j < 16; j++) kv[j] = kp[lane + 32 * j];
        float em = 0.f;
        #pragma unroll
        for (int j = 0; j < 16; j++) em += vmr[j] * tanha(qm[j] + kv[j]);
        #pragma unroll
        for (int off = 16; off; off >>= 1) em += __shfl_down_sync(0xffffffffu, em, off);
        if (lane == 0) g_me[b * S_ + s] = em + cm;
    }
}

// ---------------- K2: find cutoff Z (cumprod underflow) ------------
// Bit-identical replica of k_scan2's cumprod over [0, MONO_S_).
__global__ void __launch_bounds__(MONO_S_) k_scan1(const float* __restrict__ noise) {
    int b = blockIdx.x, s = threadIdx.x;      // 384 threads = 12 warps
    int lane = s & 31, wid = s >> 5;
    __shared__ float wa[32];
    __shared__ int warp_first[MONO_TILES_];

    float e  = g_me[b * S_ + s];
    float nz = noise[b * S_ + s];
    float p = 1.f / (1.f + __expf(-(e + nz)));
    float omp = 1.f - p;

    float x = omp;
    #pragma unroll
    for (int o = 1; o < 32; o <<= 1) {
        float y = __shfl_up_sync(0xffffffffu, x, o);
        if (lane >= o) x *= y;
    }
    if (lane == 31) wa[wid] = x;
    if (s < 32 - MONO_TILES_) wa[MONO_TILES_ + s] = 1.f;   // pad to 32 warps
    __syncthreads();
    if (wid == 0) {
        float a = wa[lane];
        #pragma unroll
        for (int o = 1; o < 32; o <<= 1) {
            float y = __shfl_up_sync(0xffffffffu, a, o);
            if (lane >= o) a *= y;
        }
        wa[lane] = a;
    }
    __syncthreads();
    float ip = wid ? x * wa[wid - 1] : x;     // inclusive cumprod, same as scan2

    unsigned zb = __ballot_sync(0xffffffffu, ip == 0.f);
    if (lane == 0) warp_first[wid] = zb ? (wid * 32 + __ffs(zb) - 1) : 0x7fffffff;
    __syncthreads();
    if (s == 0) {
        int Z = 0x7fffffff;
        #pragma unroll
        for (int i = 0; i < MONO_TILES_; i++) Z = min(Z, warp_first[i]);
        g_cut[b] = (Z <= MONO_S_ - 33) ? Z + 32 : 1024;   // margin, else full fallback
    }
}

// ---------------- K3: chunk energy for s <= cut (+ mono fallback) --
__global__ void __launch_bounds__(256) k_chunk(
        const float* __restrict__ key,
        const float* __restrict__ vbm, const float* __restrict__ rm,
        const float* __restrict__ vbc, const float* __restrict__ rc) {
    int b = blockIdx.y, tile = blockIdx.x;    // tile 0..31
    int cut = g_cut[b];
    if (tile * 32 > cut) return;
    bool do_mono = (cut >= 1024) && (tile >= MONO_TILES_);

    int t = threadIdx.x, w = t >> 5, lane = t & 31;
    __shared__ float sq[2048];   // [qm 512 | qc 512 | vm 512 | vc 512]
    {
        const float4* qm4 = reinterpret_cast<const float4*>(g_qbm + b * ATT_);
        const float4* qc4 = reinterpret_cast<const float4*>(g_qbc + b * ATT_);
        const float4* vm4 = reinterpret_cast<const float4*>(g_vnm);
        const float4* vc4 = reinterpret_cast<const float4*>(g_vnc);
        float4* s4 = reinterpret_cast<float4*>(sq);
        if (t < 128) {
            s4[t]       = qm4[t];
            s4[256 + t] = vm4[t];
        } else {
            int u = t - 128;
            s4[128 + u] = qc4[u];
            s4[384 + u] = vc4[u];
        }
    }
    __syncthreads();

    float qm[16], qc[16], vmr[16], vcr[16];
    #pragma unroll
    for (int j = 0; j < 16; j++) {
        qm[j]  = sq[lane + 32 * j];
        qc[j]  = sq[512 + lane + 32 * j];
        vmr[j] = sq[1024 + lane + 32 * j];
        vcr[j] = sq[1536 + lane + 32 * j];
    }
    const float cm = __ldg(vbm) + __ldg(rm);
    const float cc = __ldg(vbc) + __ldg(rc);

    int s0 = tile * 32 + w * 4;
    #pragma unroll
    for (int r = 0; r < 4; r++) {
        int s = s0 + r;
        const float* kp = key + (((size_t)b * S_ + s) << 9);
        float kv[16];
        #pragma unroll
        for (int j = 0; j < 16; j++) kv[j] = kp[lane + 32 * j];
        float ec = 0.f;
        #pragma unroll
        for (int j = 0; j < 16; j++) ec += vcr[j] * tanha(qc[j] + kv[j]);
        #pragma unroll
        for (int off = 16; off; off >>= 1) ec += __shfl_down_sync(0xffffffffu, ec, off);
        if (lane == 0) g_ce[b * S_ + s] = ec + cc;
        if (do_mono) {
            float em = 0.f;
            #pragma unroll
            for (int j = 0; j < 16; j++) em += vmr[j] * tanha(qm[j] + kv[j]);
            #pragma unroll
            for (int off = 16; off; off >>= 1) em += __shfl_down_sync(0xffffffffu, em, off);
            if (lane == 0) g_me[b * S_ + s] = em + cm;
        }
    }
}

// ---------------- K4: per-batch scans + windows -> beta -----------
__global__ void __launch_bounds__(1024) k_scan2(const float* __restrict__ noise,
                                                const float* __restrict__ prev) {
    int b = blockIdx.x, s = threadIdx.x;   // 1024 threads
    int lane = s & 31, wid = s >> 5;
    const int base = b * S_;
    const int cut = g_cut[b];
    const bool dead = (s > cut);           // provably-zero zone
    __shared__ float smA[S_];
    __shared__ float smC[S_];
    __shared__ float wa[32], wb[32], wc[32];
    __shared__ float s_psum;

    float e  = g_me[base + s];
    float nz = noise[base + s];
    float pv = prev[base + s];
    float c  = g_ce[base + s];
    smC[s] = c;

    float p = dead ? 0.f : 1.f / (1.f + __expf(-(e + nz)));
    if (s == S_ - 1 && !dead) p = 1.f;
    float omp = dead ? 1.f : (1.f - p);

    float x = omp;
    #pragma unroll
    for (int o = 1; o < 32; o <<= 1) {
        float y = __shfl_up_sync(0xffffffffu, x, o);
        if (lane >= o) x *= y;
    }
    if (lane == 31) wa[wid] = x;
    float ts = pv;
    #pragma unroll
    for (int off = 16; off; off >>= 1) ts += __shfl_down_sync(0xffffffffu, ts, off);
    if (lane == 0) wb[wid] = ts;
    __syncthreads();                                        // B1

    if (wid == 0) {
        float a = wa[lane];
        #pragma unroll
        for (int o = 1; o < 32; o <<= 1) {
            float y = __shfl_up_sync(0xffffffffu, a, o);
            if (lane >= o) a *= y;
        }
        wa[lane] = a;
    } else if (wid == 1) {
        float a = wb[lane];
        #pragma unroll
        for (int off = 16; off; off >>= 1) a += __shfl_down_sync(0xffffffffu, a, off);
        if (lane == 0) s_psum = a;
    }
    __syncthreads();                                        // B2

    float ip = wid ? x * wa[wid - 1] : x;
    smA[s] = ip;
    __syncthreads();                                        // B3

    float cp = s ? smA[s - 1] : 1.f;
    float cpc = fminf(fmaxf(cp, 1e-20f), 1.f);
    float y2 = dead ? 0.f : (pv / s_psum) / cpc;

    float xs = y2;
    #pragma unroll
    for (int o = 1; o < 32; o <<= 1) {
        float y = __shfl_up_sync(0xffffffffu, xs, o);
        if (lane >= o) xs += y;
    }
    if (lane == 31) wc[wid] = xs;
    __syncthreads();                                        // B4
    if (wid == 0) {
        float a = wc[lane];
        #pragma unroll
        for (int o = 1; o < 32; o <<= 1) {
            float y = __shfl_up_sync(0xffffffffu, a, o);
            if (lane >= o) a += y;
        }
        wc[lane] = a;
    }
    __syncthreads();                                        // B5
    float cs = wid ? xs + wc[wid - 1] : xs;
    float alpha = p * cp * cs;                              // dead -> exactly 0

    float mx = c;
    #pragma unroll
    for (int j = 1; j < W_; j++) { int i = s - j; if (i >= 0) mx = fmaxf(mx, smC[i]); }
    float eu = __expf(c - mx);                              // <= 1, never inf
    smA[s] = eu;
    __syncthreads();                                        // B6

    float den = 0.f;
    #pragma unroll
    for (int j = 0; j < W_; j++) { int i = s - j; if (i >= 0) den += smA[i]; }
    den = fmaxf(den, 1e-10f);
    float g = dead ? 0.f : alpha / den;
    smC[s] = g;
    __syncthreads();                                        // B7

    float acc = 0.f;
    #pragma unroll
    for (int j = 0; j < W_; j++) { int i = s + j; if (i < S_) acc += smC[i]; }
    g_beta[base + s] = dead ? 0.f : eu * acc;
}

// ---------------- K5: context = beta . value ----------------------
#define SCHUNK_ 16
__global__ void __launch_bounds__(256) k_ctx(const float* __restrict__ value,
                                             float* __restrict__ out) {
    int b = blockIdx.y, sc = blockIdx.x;     // 64 chunks of 16 rows
    if (sc * SCHUNK_ > g_cut[b]) return;     // beta exactly 0 there
    int t = threadIdx.x;
    __shared__ float sb[SCHUNK_];
    if (t < SCHUNK_) sb[t] = g_beta[b * S_ + sc * SCHUNK_ + t];
    __syncthreads();
    const float* vp = value + (((size_t)b * S_ + sc * SCHUNK_) << 9);
    float a0 = 0.f, a1 = 0.f;
    #pragma unroll
    for (int s = 0; s < SCHUNK_; s++) {
        float bs = sb[s];
        a0 += bs * vp[(s << 9) + t];
        a1 += bs * vp[(s << 9) + t + 256];
    }
    atomicAdd(out + b * 512 + t,       a0);
    atomicAdd(out + b * 512 + t + 256, a1);
}

// ---------------- launch ------------------------------------------
extern "C" void kernel_launch(void* const* d_in, const int* in_sizes, int n_in,
                              void* d_out, int out_size) {
    const float* dec   = (const float*)d_in[0];
    const float* key   = (const float*)d_in[1];
    const float* value = (const float*)d_in[2];
    const float* prev  = (const float*)d_in[3];
    const float* noise = (const float*)d_in[4];
    const float* Wm    = (const float*)d_in[5];
    const float* bm    = (const float*)d_in[6];
    const float* vm    = (const float*)d_in[7];
    const float* gm    = (const float*)d_in[8];
    const float* vbm   = (const float*)d_in[9];
    const float* rm    = (const float*)d_in[10];
    const float* Wc    = (const float*)d_in[11];
    const float* bc    = (const float*)d_in[12];
    const float* vc    = (const float*)d_in[13];
    const float* gc    = (const float*)d_in[14];
    const float* vbc   = (const float*)d_in[15];
    const float* rc    = (const float*)d_in[16];
    float* out = (float*)d_out;

    k_pre<<<dim3(32, 3), 256>>>(dec, Wm, bm, Wc, bc, vm, gm, vc, gc, out);
    k_mono<<<dim3(MONO_TILES_, B_), 256>>>(key, vbm, rm);
    k_scan1<<<B_, MONO_S_>>>(noise);
    k_chunk<<<dim3(S_ / 32, B_), 256>>>(key, vbm, rm, vbc, rc);
    k_scan2<<<B_, S_>>>(noise, prev);
    k_ctx<<<dim3(S_ / SCHUNK_, B_), 256>>>(value, out);
}

// round 10
// speedup vs baseline: 1.1380x; 1.1380x over previous
#include <cuda_runtime.h>

#define B_   32
#define S_   1024
#define ATT_ 512
#define W_   8
#define MONO_S_ 384   // energies precomputed for s < MONO_S_
#define MONO_TILES_ 12

// ---------------- scratch (no allocations allowed) ----------------
__device__ float g_qbm[B_ * ATT_];   // dec_h @ Wm^T + bm
__device__ float g_qbc[B_ * ATT_];   // dec_h @ Wc^T + bc
__device__ float g_vnm[ATT_];        // gm * vm / ||vm||
__device__ float g_vnc[ATT_];
__device__ float g_me[B_ * S_];      // monotonic energy
__device__ float g_ce[B_ * S_];      // chunk energy
__device__ float g_beta[B_ * S_];
__device__ int   g_cut[B_];          // per-batch active cutoff (inclusive)

__device__ __forceinline__ float tanha(float x) {
    float y;
    asm("tanh.approx.f32 %0, %1;" : "=f"(y) : "f"(x));
    return y;
}

// ---------------- K0: matvec + vnorm + zero (fused pre-pass) ------
__global__ void __launch_bounds__(256) k_pre(
        const float* __restrict__ dec,
        const float* __restrict__ Wm, const float* __restrict__ bm,
        const float* __restrict__ Wc, const float* __restrict__ bc,
        const float* __restrict__ vm, const float* __restrict__ gm,
        const float* __restrict__ vc, const float* __restrict__ gc,
        float* __restrict__ out) {
    int t = threadIdx.x;

    if (blockIdx.y == 2) {
        int x = blockIdx.x;
        out[x * 512 + t] = 0.f;
        out[x * 512 + 256 + t] = 0.f;
        if (x > 1) return;
        const float* v = x ? vc : vm;
        const float* g = x ? gc : gm;
        float* o       = x ? g_vnc : g_vnm;
        float x1 = v[t], x2 = v[t + 256];
        float ss = x1 * x1 + x2 * x2;
        __shared__ float red[8];
        #pragma unroll
        for (int off = 16; off; off >>= 1) ss += __shfl_down_sync(0xffffffffu, ss, off);
        if ((t & 31) == 0) red[t >> 5] = ss;
        __syncthreads();
        __shared__ float s_scale;
        if (t == 0) {
            float a = red[0] + red[1] + red[2] + red[3] + red[4] + red[5] + red[6] + red[7];
            s_scale = __ldg(g) / sqrtf(a);
        }
        __syncthreads();
        o[t] = x1 * s_scale;
        o[t + 256] = x2 * s_scale;
        return;
    }

    const float* W    = blockIdx.y ? Wc : Wm;
    const float* bias = blockIdx.y ? bc : bm;
    float* qout       = blockIdx.y ? g_qbc : g_qbm;

    int w = t >> 5, lane = t & 31;
    int row0 = blockIdx.x * 16 + w * 2;          // 2 rows per warp

    const float4* W40 = reinterpret_cast<const float4*>(W + (size_t)row0 * 512);
    const float4* W41 = reinterpret_cast<const float4*>(W + (size_t)(row0 + 1) * 512);
    float4 w0[4], w1[4];
    #pragma unroll
    for (int j = 0; j < 4; j++) { w0[j] = W40[lane + 32 * j]; w1[j] = W41[lane + 32 * j]; }
    float bias0 = bias[row0], bias1 = bias[row0 + 1];

    __shared__ float4 sdec[16 * 128];            // 32 KB: 16 batches
    const float4* dec4 = reinterpret_cast<const float4*>(dec);

    #pragma unroll
    for (int half = 0; half < 2; half++) {
        #pragma unroll
        for (int i = t; i < 2048; i += 256) sdec[i] = dec4[half * 2048 + i];
        __syncthreads();
        #pragma unroll 4
        for (int bb = 0; bb < 16; bb++) {
            int b = half * 16 + bb;
            float a0 = 0.f, a1 = 0.f;
            #pragma unroll
            for (int j = 0; j < 4; j++) {
                float4 dv = sdec[bb * 128 + lane + 32 * j];
                a0 += w0[j].x * dv.x + w0[j].y * dv.y + w0[j].z * dv.z + w0[j].w * dv.w;
                a1 += w1[j].x * dv.x + w1[j].y * dv.y + w1[j].z * dv.z + w1[j].w * dv.w;
            }
            #pragma unroll
            for (int off = 16; off; off >>= 1) {
                a0 += __shfl_down_sync(0xffffffffu, a0, off);
                a1 += __shfl_down_sync(0xffffffffu, a1, off);
            }
            if (lane == 0) {
                qout[b * ATT_ + row0]     = a0 + bias0;
                qout[b * ATT_ + row0 + 1] = a1 + bias1;
            }
        }
        __syncthreads();
    }
}

// ---------------- K1: both energies, one key pass -----------------
// q/v vectors read from smem per use (conflict-free) -> ~40 regs,
// high occupancy. tile_base=0 for head (s<384); tail run guarded by cut.
__global__ void __launch_bounds__(256) k_both(
        const float* __restrict__ key,
        const float* __restrict__ vbm, const float* __restrict__ rm,
        const float* __restrict__ vbc, const float* __restrict__ rc,
        int tile_base, int check_cut) {
    int b = blockIdx.y;
    int tile = blockIdx.x + tile_base;
    if (check_cut && g_cut[b] != 1024) return;   // tail: only on fallback
    int t = threadIdx.x, w = t >> 5, lane = t & 31;

    __shared__ float sq[2048];   // [qm 512 | qc 512 | vm 512 | vc 512]
    {
        const float4* qm4 = reinterpret_cast<const float4*>(g_qbm + b * ATT_);
        const float4* qc4 = reinterpret_cast<const float4*>(g_qbc + b * ATT_);
        const float4* vm4 = reinterpret_cast<const float4*>(g_vnm);
        const float4* vc4 = reinterpret_cast<const float4*>(g_vnc);
        float4* s4 = reinterpret_cast<float4*>(sq);
        if (t < 128) {
            s4[t]       = qm4[t];
            s4[256 + t] = vm4[t];
        } else {
            int u = t - 128;
            s4[128 + u] = qc4[u];
            s4[384 + u] = vc4[u];
        }
    }
    __syncthreads();

    const float cm = __ldg(vbm) + __ldg(rm);
    const float cc = __ldg(vbc) + __ldg(rc);

    int s0 = tile * 32 + w * 4;
    #pragma unroll
    for (int r = 0; r < 4; r++) {
        int s = s0 + r;
        const float* kp = key + (((size_t)b * S_ + s) << 9);
        float kv[16];
        #pragma unroll
        for (int j = 0; j < 16; j++) kv[j] = kp[lane + 32 * j];
        float em = 0.f, ec = 0.f;
        #pragma unroll
        for (int j = 0; j < 16; j++) {
            int idx = lane + 32 * j;
            em += sq[1024 + idx] * tanha(sq[idx] + kv[j]);
            ec += sq[1536 + idx] * tanha(sq[512 + idx] + kv[j]);
        }
        #pragma unroll
        for (int off = 16; off; off >>= 1) {
            em += __shfl_down_sync(0xffffffffu, em, off);
            ec += __shfl_down_sync(0xffffffffu, ec, off);
        }
        if (lane == 0) {
            g_me[b * S_ + s] = em + cm;
            g_ce[b * S_ + s] = ec + cc;
        }
    }
}

// ---------------- K2: find cutoff Z (cumprod underflow) ------------
__global__ void __launch_bounds__(MONO_S_) k_scan1(const float* __restrict__ noise) {
    int b = blockIdx.x, s = threadIdx.x;      // 384 threads = 12 warps
    int lane = s & 31, wid = s >> 5;
    __shared__ float wa[32];
    __shared__ int warp_first[MONO_TILES_];

    float e  = g_me[b * S_ + s];
    float nz = noise[b * S_ + s];
    float p = 1.f / (1.f + __expf(-(e + nz)));
    float omp = 1.f - p;

    float x = omp;
    #pragma unroll
    for (int o = 1; o < 32; o <<= 1) {
        float y = __shfl_up_sync(0xffffffffu, x, o);
        if (lane >= o) x *= y;
    }
    if (lane == 31) wa[wid] = x;
    if (s < 32 - MONO_TILES_) wa[MONO_TILES_ + s] = 1.f;   // pad to 32 warps
    __syncthreads();
    if (wid == 0) {
        float a = wa[lane];
        #pragma unroll
        for (int o = 1; o < 32; o <<= 1) {
            float y = __shfl_up_sync(0xffffffffu, a, o);
            if (lane >= o) a *= y;
        }
        wa[lane] = a;
    }
    __syncthreads();
    float ip = wid ? x * wa[wid - 1] : x;     // inclusive cumprod, same as scan2

    unsigned zb = __ballot_sync(0xffffffffu, ip == 0.f);
    if (lane == 0) warp_first[wid] = zb ? (wid * 32 + __ffs(zb) - 1) : 0x7fffffff;
    __syncthreads();
    if (s == 0) {
        int Z = 0x7fffffff;
        #pragma unroll
        for (int i = 0; i < MONO_TILES_; i++) Z = min(Z, warp_first[i]);
        g_cut[b] = (Z <= MONO_S_ - 33) ? Z + 32 : 1024;   // margin, else full fallback
    }
}

// ---------------- K3: per-batch scans + windows -> beta -----------
__global__ void __launch_bounds__(1024) k_scan2(const float* __restrict__ noise,
                                                const float* __restrict__ prev) {
    int b = blockIdx.x, s = threadIdx.x;   // 1024 threads
    int lane = s & 31, wid = s >> 5;
    const int base = b * S_;
    const int cut = g_cut[b];
    const bool dead = (s > cut);           // provably-zero zone
    __shared__ float smA[S_];
    __shared__ float smC[S_];
    __shared__ float wa[32], wb[32], wc[32];
    __shared__ float s_psum;

    float e  = g_me[base + s];
    float nz = noise[base + s];
    float pv = prev[base + s];
    float c  = g_ce[base + s];
    smC[s] = c;

    float p = dead ? 0.f : 1.f / (1.f + __expf(-(e + nz)));
    if (s == S_ - 1 && !dead) p = 1.f;
    float omp = dead ? 1.f : (1.f - p);

    float x = omp;
    #pragma unroll
    for (int o = 1; o < 32; o <<= 1) {
        float y = __shfl_up_sync(0xffffffffu, x, o);
        if (lane >= o) x *= y;
    }
    if (lane == 31) wa[wid] = x;
    float ts = pv;
    #pragma unroll
    for (int off = 16; off; off >>= 1) ts += __shfl_down_sync(0xffffffffu, ts, off);
    if (lane == 0) wb[wid] = ts;
    __syncthreads();                                        // B1

    if (wid == 0) {
        float a = wa[lane];
        #pragma unroll
        for (int o = 1; o < 32; o <<= 1) {
            float y = __shfl_up_sync(0xffffffffu, a, o);
            if (lane >= o) a *= y;
        }
        wa[lane] = a;
    } else if (wid == 1) {
        float a = wb[lane];
        #pragma unroll
        for (int off = 16; off; off >>= 1) a += __shfl_down_sync(0xffffffffu, a, off);
        if (lane == 0) s_psum = a;
    }
    __syncthreads();                                        // B2

    float ip = wid ? x * wa[wid - 1] : x;
    smA[s] = ip;
    __syncthreads();                                        // B3

    float cp = s ? smA[s - 1] : 1.f;
    float cpc = fminf(fmaxf(cp, 1e-20f), 1.f);
    float y2 = dead ? 0.f : (pv / s_psum) / cpc;

    float xs = y2;
    #pragma unroll
    for (int o = 1; o < 32; o <<= 1) {
        float y = __shfl_up_sync(0xffffffffu, xs, o);
        if (lane >= o) xs += y;
    }
    if (lane == 31) wc[wid] = xs;
    __syncthreads();                                        // B4
    if (wid == 0) {
        float a = wc[lane];
        #pragma unroll
        for (int o = 1; o < 32; o <<= 1) {
            float y = __shfl_up_sync(0xffffffffu, a, o);
            if (lane >= o) a += y;
        }
        wc[lane] = a;
    }
    __syncthreads();                                        // B5
    float cs = wid ? xs + wc[wid - 1] : xs;
    float alpha = p * cp * cs;                              // dead -> exactly 0

    float mx = c;
    #pragma unroll
    for (int j = 1; j < W_; j++) { int i = s - j; if (i >= 0) mx = fmaxf(mx, smC[i]); }
    float eu = __expf(c - mx);                              // <= 1, never inf
    smA[s] = eu;
    __syncthreads();                                        // B6

    float den = 0.f;
    #pragma unroll
    for (int j = 0; j < W_; j++) { int i = s - j; if (i >= 0) den += smA[i]; }
    den = fmaxf(den, 1e-10f);
    float g = dead ? 0.f : alpha / den;
    smC[s] = g;
    __syncthreads();                                        // B7

    float acc = 0.f;
    #pragma unroll
    for (int j = 0; j < W_; j++) { int i = s + j; if (i < S_) acc += smC[i]; }
    g_beta[base + s] = dead ? 0.f : eu * acc;
}

// ---------------- K4: context = beta . value ----------------------
#define SCHUNK_ 16
__global__ void __launch_bounds__(256) k_ctx(const float* __restrict__ value,
                                             float* __restrict__ out) {
    int b = blockIdx.y, sc = blockIdx.x;     // 64 chunks of 16 rows
    if (sc * SCHUNK_ > g_cut[b]) return;     // beta exactly 0 there
    int t = threadIdx.x;
    __shared__ float sb[SCHUNK_];
    if (t < SCHUNK_) sb[t] = g_beta[b * S_ + sc * SCHUNK_ + t];
    __syncthreads();
    const float* vp = value + (((size_t)b * S_ + sc * SCHUNK_) << 9);
    float a0 = 0.f, a1 = 0.f;
    #pragma unroll
    for (int s = 0; s < SCHUNK_; s++) {
        float bs = sb[s];
        a0 += bs * vp[(s << 9) + t];
        a1 += bs * vp[(s << 9) + t + 256];
    }
    atomicAdd(out + b * 512 + t,       a0);
    atomicAdd(out + b * 512 + t + 256, a1);
}

// ---------------- launch ------------------------------------------
extern "C" void kernel_launch(void* const* d_in, const int* in_sizes, int n_in,
                              void* d_out, int out_size) {
    const float* dec   = (const float*)d_in[0];
    const float* key   = (const float*)d_in[1];
    const float* value = (const float*)d_in[2];
    const float* prev  = (const float*)d_in[3];
    const float* noise = (const float*)d_in[4];
    const float* Wm    = (const float*)d_in[5];
    const float* bm    = (const float*)d_in[6];
    const float* vm    = (const float*)d_in[7];
    const float* gm    = (const float*)d_in[8];
    const float* vbm   = (const float*)d_in[9];
    const float* rm    = (const float*)d_in[10];
    const float* Wc    = (const float*)d_in[11];
    const float* bc    = (const float*)d_in[12];
    const float* vc    = (const float*)d_in[13];
    const float* gc    = (const float*)d_in[14];
    const float* vbc   = (const float*)d_in[15];
    const float* rc    = (const float*)d_in[16];
    float* out = (float*)d_out;

    k_pre<<<dim3(32, 3), 256>>>(dec, Wm, bm, Wc, bc, vm, gm, vc, gc, out);
    // head: both energies for s < 384 (one pass over the live key region)
    k_both<<<dim3(MONO_TILES_, B_), 256>>>(key, vbm, rm, vbc, rc, 0, 0);
    k_scan1<<<B_, MONO_S_>>>(noise);
    // tail insurance: s in [384, 1024), runs only if a batch never underflowed
    k_both<<<dim3(S_ / 32 - MONO_TILES_, B_), 256>>>(key, vbm, rm, vbc, rc,
                                                     MONO_TILES_, 1);
    k_scan2<<<B_, S_>>>(noise, prev);
    k_ctx<<<dim3(S_ / SCHUNK_, B_), 256>>>(value, out);
}

// round 11
// speedup vs baseline: 1.1493x; 1.0099x over previous
#include <cuda_runtime.h>

#define B_   32
#define S_   1024
#define ATT_ 512
#define W_   8
#define MONO_S_ 384   // energies precomputed for s < MONO_S_
#define MONO_TILES_ 12

// ---------------- scratch (no allocations allowed) ----------------
__device__ float g_qbm[B_ * ATT_];   // dec_h @ Wm^T + bm
__device__ float g_qbc[B_ * ATT_];   // dec_h @ Wc^T + bc
__device__ float g_vnm[ATT_];        // gm * vm / ||vm||
__device__ float g_vnc[ATT_];
__device__ float g_me[B_ * S_];      // monotonic energy
__device__ float g_ce[B_ * S_];      // chunk energy
__device__ float g_beta[B_ * S_];
__device__ int   g_cut[B_];          // per-batch active cutoff (inclusive)

__device__ __forceinline__ float tanha(float x) {
    float y;
    asm("tanh.approx.f32 %0, %1;" : "=f"(y) : "f"(x));
    return y;
}

// ---------------- K0: matvec + vnorm + zero (fused pre-pass) ------
__global__ void __launch_bounds__(256) k_pre(
        const float* __restrict__ dec,
        const float* __restrict__ Wm, const float* __restrict__ bm,
        const float* __restrict__ Wc, const float* __restrict__ bc,
        const float* __restrict__ vm, const float* __restrict__ gm,
        const float* __restrict__ vc, const float* __restrict__ gc,
        float* __restrict__ out) {
    int t = threadIdx.x;

    if (blockIdx.y == 2) {
        int x = blockIdx.x;
        out[x * 512 + t] = 0.f;
        out[x * 512 + 256 + t] = 0.f;
        if (x > 1) return;
        const float* v = x ? vc : vm;
        const float* g = x ? gc : gm;
        float* o       = x ? g_vnc : g_vnm;
        float x1 = v[t], x2 = v[t + 256];
        float ss = x1 * x1 + x2 * x2;
        __shared__ float red[8];
        #pragma unroll
        for (int off = 16; off; off >>= 1) ss += __shfl_down_sync(0xffffffffu, ss, off);
        if ((t & 31) == 0) red[t >> 5] = ss;
        __syncthreads();
        __shared__ float s_scale;
        if (t == 0) {
            float a = red[0] + red[1] + red[2] + red[3] + red[4] + red[5] + red[6] + red[7];
            s_scale = __ldg(g) / sqrtf(a);
        }
        __syncthreads();
        o[t] = x1 * s_scale;
        o[t + 256] = x2 * s_scale;
        return;
    }

    const float* W    = blockIdx.y ? Wc : Wm;
    const float* bias = blockIdx.y ? bc : bm;
    float* qout       = blockIdx.y ? g_qbc : g_qbm;

    int w = t >> 5, lane = t & 31;
    int row0 = blockIdx.x * 16 + w * 2;          // 2 rows per warp

    const float4* W40 = reinterpret_cast<const float4*>(W + (size_t)row0 * 512);
    const float4* W41 = reinterpret_cast<const float4*>(W + (size_t)(row0 + 1) * 512);
    float4 w0[4], w1[4];
    #pragma unroll
    for (int j = 0; j < 4; j++) { w0[j] = W40[lane + 32 * j]; w1[j] = W41[lane + 32 * j]; }
    float bias0 = bias[row0], bias1 = bias[row0 + 1];

    __shared__ float4 sdec[16 * 128];            // 32 KB: 16 batches
    const float4* dec4 = reinterpret_cast<const float4*>(dec);

    #pragma unroll
    for (int half = 0; half < 2; half++) {
        #pragma unroll
        for (int i = t; i < 2048; i += 256) sdec[i] = dec4[half * 2048 + i];
        __syncthreads();
        #pragma unroll 4
        for (int bb = 0; bb < 16; bb++) {
            int b = half * 16 + bb;
            float a0 = 0.f, a1 = 0.f;
            #pragma unroll
            for (int j = 0; j < 4; j++) {
                float4 dv = sdec[bb * 128 + lane + 32 * j];
                a0 += w0[j].x * dv.x + w0[j].y * dv.y + w0[j].z * dv.z + w0[j].w * dv.w;
                a1 += w1[j].x * dv.x + w1[j].y * dv.y + w1[j].z * dv.z + w1[j].w * dv.w;
            }
            #pragma unroll
            for (int off = 16; off; off >>= 1) {
                a0 += __shfl_down_sync(0xffffffffu, a0, off);
                a1 += __shfl_down_sync(0xffffffffu, a1, off);
            }
            if (lane == 0) {
                qout[b * ATT_ + row0]     = a0 + bias0;
                qout[b * ATT_ + row0 + 1] = a1 + bias1;
            }
        }
        __syncthreads();
    }
}

// ---------------- K1: both energies for s < MONO_S_ (one key pass) -
__global__ void __launch_bounds__(256) k_both(
        const float* __restrict__ key,
        const float* __restrict__ vbm, const float* __restrict__ rm,
        const float* __restrict__ vbc, const float* __restrict__ rc) {
    int b = blockIdx.y;
    int tile = blockIdx.x;
    int t = threadIdx.x, w = t >> 5, lane = t & 31;

    __shared__ float sq[2048];   // [qm 512 | qc 512 | vm 512 | vc 512]
    {
        const float4* qm4 = reinterpret_cast<const float4*>(g_qbm + b * ATT_);
        const float4* qc4 = reinterpret_cast<const float4*>(g_qbc + b * ATT_);
        const float4* vm4 = reinterpret_cast<const float4*>(g_vnm);
        const float4* vc4 = reinterpret_cast<const float4*>(g_vnc);
        float4* s4 = reinterpret_cast<float4*>(sq);
        if (t < 128) {
            s4[t]       = qm4[t];
            s4[256 + t] = vm4[t];
        } else {
            int u = t - 128;
            s4[128 + u] = qc4[u];
            s4[384 + u] = vc4[u];
        }
    }
    __syncthreads();

    const float cm = __ldg(vbm) + __ldg(rm);
    const float cc = __ldg(vbc) + __ldg(rc);

    int s0 = tile * 32 + w * 4;
    #pragma unroll
    for (int r = 0; r < 4; r++) {
        int s = s0 + r;
        const float* kp = key + (((size_t)b * S_ + s) << 9);
        float kv[16];
        #pragma unroll
        for (int j = 0; j < 16; j++) kv[j] = kp[lane + 32 * j];
        float em = 0.f, ec = 0.f;
        #pragma unroll
        for (int j = 0; j < 16; j++) {
            int idx = lane + 32 * j;
            em += sq[1024 + idx] * tanha(sq[idx] + kv[j]);
            ec += sq[1536 + idx] * tanha(sq[512 + idx] + kv[j]);
        }
        #pragma unroll
        for (int off = 16; off; off >>= 1) {
            em += __shfl_down_sync(0xffffffffu, em, off);
            ec += __shfl_down_sync(0xffffffffu, ec, off);
        }
        if (lane == 0) {
            g_me[b * S_ + s] = em + cm;
            g_ce[b * S_ + s] = ec + cc;
        }
    }
}

// ---------------- K2: find cutoff Z (cumprod underflow) ------------
__global__ void __launch_bounds__(MONO_S_) k_scan1(const float* __restrict__ noise) {
    int b = blockIdx.x, s = threadIdx.x;      // 384 threads = 12 warps
    int lane = s & 31, wid = s >> 5;
    __shared__ float wa[32];
    __shared__ int warp_first[MONO_TILES_];

    float e  = g_me[b * S_ + s];
    float nz = noise[b * S_ + s];
    float p = 1.f / (1.f + __expf(-(e + nz)));
    float omp = 1.f - p;

    float x = omp;
    #pragma unroll
    for (int o = 1; o < 32; o <<= 1) {
        float y = __shfl_up_sync(0xffffffffu, x, o);
        if (lane >= o) x *= y;
    }
    if (lane == 31) wa[wid] = x;
    if (s < 32 - MONO_TILES_) wa[MONO_TILES_ + s] = 1.f;   // pad to 32 warps
    __syncthreads();
    if (wid == 0) {
        float a = wa[lane];
        #pragma unroll
        for (int o = 1; o < 32; o <<= 1) {
            float y = __shfl_up_sync(0xffffffffu, a, o);
            if (lane >= o) a *= y;
        }
        wa[lane] = a;
    }
    __syncthreads();
    float ip = wid ? x * wa[wid - 1] : x;     // inclusive cumprod, same as scan2

    unsigned zb = __ballot_sync(0xffffffffu, ip == 0.f);
    if (lane == 0) warp_first[wid] = zb ? (wid * 32 + __ffs(zb) - 1) : 0x7fffffff;
    __syncthreads();
    if (s == 0) {
        int Z = 0x7fffffff;
        #pragma unroll
        for (int i = 0; i < MONO_TILES_; i++) Z = min(Z, warp_first[i]);
        g_cut[b] = (Z <= MONO_S_ - 33) ? Z + 32 : 1024;   // margin, else full fallback
    }
}

// ---------------- K3: scans + windows -> beta (w/ inline fallback) -
__global__ void __launch_bounds__(1024) k_scan2(
        const float* __restrict__ noise, const float* __restrict__ prev,
        const float* __restrict__ key,
        const float* __restrict__ vbm, const float* __restrict__ rm,
        const float* __restrict__ vbc, const float* __restrict__ rc) {
    int b = blockIdx.x, s = threadIdx.x;   // 1024 threads
    int lane = s & 31, wid = s >> 5;
    const int base = b * S_;
    const int cut = g_cut[b];
    const bool dead = (s > cut);           // provably-zero zone
    __shared__ float smA[S_];
    __shared__ float smC[S_];
    __shared__ float wa[32], wb[32], wc[32];
    __shared__ float s_psum;

    float e  = g_me[base + s];
    float nz = noise[base + s];
    float pv = prev[base + s];
    float c  = g_ce[base + s];

    // insurance: if no underflow was found in [0,384), energies for
    // s >= 384 were never computed -- compute them inline (rare path).
    if (cut >= 1024 && s >= MONO_S_) {
        const float cm = __ldg(vbm) + __ldg(rm);
        const float cc = __ldg(vbc) + __ldg(rc);
        const float* kp = key + (((size_t)base + s) << 9);
        const float* qm = g_qbm + b * ATT_;
        const float* qc = g_qbc + b * ATT_;
        float em = 0.f, ec = 0.f;
        for (int j = 0; j < ATT_; j++) {
            float kvj = kp[j];
            em += g_vnm[j] * tanha(qm[j] + kvj);
            ec += g_vnc[j] * tanha(qc[j] + kvj);
        }
        e = em + cm;
        c = ec + cc;
    }
    smC[s] = c;

    float p = dead ? 0.f : 1.f / (1.f + __expf(-(e + nz)));
    if (s == S_ - 1 && !dead) p = 1.f;
    float omp = dead ? 1.f : (1.f - p);

    float x = omp;
    #pragma unroll
    for (int o = 1; o < 32; o <<= 1) {
        float y = __shfl_up_sync(0xffffffffu, x, o);
        if (lane >= o) x *= y;
    }
    if (lane == 31) wa[wid] = x;
    float ts = pv;
    #pragma unroll
    for (int off = 16; off; off >>= 1) ts += __shfl_down_sync(0xffffffffu, ts, off);
    if (lane == 0) wb[wid] = ts;
    __syncthreads();                                        // B1

    if (wid == 0) {
        float a = wa[lane];
        #pragma unroll
        for (int o = 1; o < 32; o <<= 1) {
            float y = __shfl_up_sync(0xffffffffu, a, o);
            if (lane >= o) a *= y;
        }
        wa[lane] = a;
    } else if (wid == 1) {
        float a = wb[lane];
        #pragma unroll
        for (int off = 16; off; off >>= 1) a += __shfl_down_sync(0xffffffffu, a, off);
        if (lane == 0) s_psum = a;
    }
    __syncthreads();                                        // B2

    float ip = wid ? x * wa[wid - 1] : x;
    smA[s] = ip;
    __syncthreads();                                        // B3

    float cp = s ? smA[s - 1] : 1.f;
    float cpc = fminf(fmaxf(cp, 1e-20f), 1.f);
    float y2 = dead ? 0.f : (pv / s_psum) / cpc;

    float xs = y2;
    #pragma unroll
    for (int o = 1; o < 32; o <<= 1) {
        float y = __shfl_up_sync(0xffffffffu, xs, o);
        if (lane >= o) xs += y;
    }
    if (lane == 31) wc[wid] = xs;
    __syncthreads();                                        // B4
    if (wid == 0) {
        float a = wc[lane];
        #pragma unroll
        for (int o = 1; o < 32; o <<= 1) {
            float y = __shfl_up_sync(0xffffffffu, a, o);
            if (lane >= o) a += y;
        }
        wc[lane] = a;
    }
    __syncthreads();                                        // B5
    float cs = wid ? xs + wc[wid - 1] : xs;
    float alpha = p * cp * cs;                              // dead -> exactly 0

    float mx = c;
    #pragma unroll
    for (int j = 1; j < W_; j++) { int i = s - j; if (i >= 0) mx = fmaxf(mx, smC[i]); }
    float eu = __expf(c - mx);                              // <= 1, never inf
    smA[s] = eu;
    __syncthreads();                                        // B6

    float den = 0.f;
    #pragma unroll
    for (int j = 0; j < W_; j++) { int i = s - j; if (i >= 0) den += smA[i]; }
    den = fmaxf(den, 1e-10f);
    float g = dead ? 0.f : alpha / den;
    smC[s] = g;
    __syncthreads();                                        // B7

    float acc = 0.f;
    #pragma unroll
    for (int j = 0; j < W_; j++) { int i = s + j; if (i < S_) acc += smC[i]; }
    g_beta[base + s] = dead ? 0.f : eu * acc;
}

// ---------------- K4: context = beta . value ----------------------
#define SCHUNK_ 16
__global__ void __launch_bounds__(256) k_ctx(const float* __restrict__ value,
                                             float* __restrict__ out) {
    int b = blockIdx.y, sc = blockIdx.x;     // 64 chunks of 16 rows
    if (sc * SCHUNK_ > g_cut[b]) return;     // beta exactly 0 there
    int t = threadIdx.x;
    __shared__ float sb[SCHUNK_];
    if (t < SCHUNK_) sb[t] = g_beta[b * S_ + sc * SCHUNK_ + t];
    __syncthreads();
    const float* vp = value + (((size_t)b * S_ + sc * SCHUNK_) << 9);
    float a0 = 0.f, a1 = 0.f;
    #pragma unroll
    for (int s = 0; s < SCHUNK_; s++) {
        float bs = sb[s];
        a0 += bs * vp[(s << 9) + t];
        a1 += bs * vp[(s << 9) + t + 256];
    }
    atomicAdd(out + b * 512 + t,       a0);
    atomicAdd(out + b * 512 + t + 256, a1);
}

// ---------------- launch ------------------------------------------
extern "C" void kernel_launch(void* const* d_in, const int* in_sizes, int n_in,
                              void* d_out, int out_size) {
    const float* dec   = (const float*)d_in[0];
    const float* key   = (const float*)d_in[1];
    const float* value = (const float*)d_in[2];
    const float* prev  = (const float*)d_in[3];
    const float* noise = (const float*)d_in[4];
    const float* Wm    = (const float*)d_in[5];
    const float* bm    = (const float*)d_in[6];
    const float* vm    = (const float*)d_in[7];
    const float* gm    = (const float*)d_in[8];
    const float* vbm   = (const float*)d_in[9];
    const float* rm    = (const float*)d_in[10];
    const float* Wc    = (const float*)d_in[11];
    const float* bc    = (const float*)d_in[12];
    const float* vc    = (const float*)d_in[13];
    const float* gc    = (const float*)d_in[14];
    const float* vbc   = (const float*)d_in[15];
    const float* rc    = (const float*)d_in[16];
    float* out = (float*)d_out;

    k_pre<<<dim3(32, 3), 256>>>(dec, Wm, bm, Wc, bc, vm, gm, vc, gc, out);
    k_both<<<dim3(MONO_TILES_, B_), 256>>>(key, vbm, rm, vbc, rc);
    k_scan1<<<B_, MONO_S_>>>(noise);
    k_scan2<<<B_, S_>>>(noise, prev, key, vbm, rm, vbc, rc);
    k_ctx<<<dim3(S_ / SCHUNK_, B_), 256>>>(value, out);
}

// round 12
// speedup vs baseline: 1.3220x; 1.1503x over previous
#include <cuda_runtime.h>

#define B_   32
#define S_   1024
#define ATT_ 512
#define W_   8
#define MONO_S_ 384   // energies precomputed for s < MONO_S_
#define MONO_TILES_ 12

// ---------------- scratch (no allocations allowed) ----------------
__device__ float g_qbm[B_ * ATT_];   // dec_h @ Wm^T + bm
__device__ float g_qbc[B_ * ATT_];   // dec_h @ Wc^T + bc
__device__ float g_vnm[ATT_];        // gm * vm / ||vm||
__device__ float g_vnc[ATT_];
__device__ float g_me[B_ * S_];      // monotonic energy (s < MONO_S_)
__device__ float g_ce[B_ * S_];      // chunk energy    (s < MONO_S_)
__device__ float g_beta[B_ * S_];
__device__ int   g_cut[B_];          // per-batch active cutoff (inclusive)

__device__ __forceinline__ float tanha(float x) {
    float y;
    asm("tanh.approx.f32 %0, %1;" : "=f"(y) : "f"(x));
    return y;
}

// ---------------- K0: matvec + vnorm + zero (fused pre-pass) ------
__global__ void __launch_bounds__(256) k_pre(
        const float* __restrict__ dec,
        const float* __restrict__ Wm, const float* __restrict__ bm,
        const float* __restrict__ Wc, const float* __restrict__ bc,
        const float* __restrict__ vm, const float* __restrict__ gm,
        const float* __restrict__ vc, const float* __restrict__ gc,
        float* __restrict__ out) {
    int t = threadIdx.x;

    if (blockIdx.y == 2) {
        int x = blockIdx.x;
        out[x * 512 + t] = 0.f;
        out[x * 512 + 256 + t] = 0.f;
        if (x > 1) return;
        const float* v = x ? vc : vm;
        const float* g = x ? gc : gm;
        float* o       = x ? g_vnc : g_vnm;
        float x1 = v[t], x2 = v[t + 256];
        float ss = x1 * x1 + x2 * x2;
        __shared__ float red[8];
        #pragma unroll
        for (int off = 16; off; off >>= 1) ss += __shfl_down_sync(0xffffffffu, ss, off);
        if ((t & 31) == 0) red[t >> 5] = ss;
        __syncthreads();
        __shared__ float s_scale;
        if (t == 0) {
            float a = red[0] + red[1] + red[2] + red[3] + red[4] + red[5] + red[6] + red[7];
            s_scale = __ldg(g) / sqrtf(a);
        }
        __syncthreads();
        o[t] = x1 * s_scale;
        o[t + 256] = x2 * s_scale;
        return;
    }

    const float* W    = blockIdx.y ? Wc : Wm;
    const float* bias = blockIdx.y ? bc : bm;
    float* qout       = blockIdx.y ? g_qbc : g_qbm;

    int w = t >> 5, lane = t & 31;
    int row0 = blockIdx.x * 16 + w * 2;          // 2 rows per warp

    const float4* W40 = reinterpret_cast<const float4*>(W + (size_t)row0 * 512);
    const float4* W41 = reinterpret_cast<const float4*>(W + (size_t)(row0 + 1) * 512);
    float4 w0[4], w1[4];
    #pragma unroll
    for (int j = 0; j < 4; j++) { w0[j] = W40[lane + 32 * j]; w1[j] = W41[lane + 32 * j]; }
    float bias0 = bias[row0], bias1 = bias[row0 + 1];

    __shared__ float4 sdec[16 * 128];            // 32 KB: 16 batches
    const float4* dec4 = reinterpret_cast<const float4*>(dec);

    #pragma unroll
    for (int half = 0; half < 2; half++) {
        #pragma unroll
        for (int i = t; i < 2048; i += 256) sdec[i] = dec4[half * 2048 + i];
        __syncthreads();
        #pragma unroll 4
        for (int bb = 0; bb < 16; bb++) {
            int b = half * 16 + bb;
            float a0 = 0.f, a1 = 0.f;
            #pragma unroll
            for (int j = 0; j < 4; j++) {
                float4 dv = sdec[bb * 128 + lane + 32 * j];
                a0 += w0[j].x * dv.x + w0[j].y * dv.y + w0[j].z * dv.z + w0[j].w * dv.w;
                a1 += w1[j].x * dv.x + w1[j].y * dv.y + w1[j].z * dv.z + w1[j].w * dv.w;
            }
            #pragma unroll
            for (int off = 16; off; off >>= 1) {
                a0 += __shfl_down_sync(0xffffffffu, a0, off);
                a1 += __shfl_down_sync(0xffffffffu, a1, off);
            }
            if (lane == 0) {
                qout[b * ATT_ + row0]     = a0 + bias0;
                qout[b * ATT_ + row0 + 1] = a1 + bias1;
            }
        }
        __syncthreads();
    }
}

// ---------------- K1: both energies for s < MONO_S_ (one key pass) -
__global__ void __launch_bounds__(256) k_both(
        const float* __restrict__ key,
        const float* __restrict__ vbm, const float* __restrict__ rm,
        const float* __restrict__ vbc, const float* __restrict__ rc) {
    int b = blockIdx.y;
    int tile = blockIdx.x;
    int t = threadIdx.x, w = t >> 5, lane = t & 31;

    __shared__ float sq[2048];   // [qm 512 | qc 512 | vm 512 | vc 512]
    {
        const float4* qm4 = reinterpret_cast<const float4*>(g_qbm + b * ATT_);
        const float4* qc4 = reinterpret_cast<const float4*>(g_qbc + b * ATT_);
        const float4* vm4 = reinterpret_cast<const float4*>(g_vnm);
        const float4* vc4 = reinterpret_cast<const float4*>(g_vnc);
        float4* s4 = reinterpret_cast<float4*>(sq);
        if (t < 128) {
            s4[t]       = qm4[t];
            s4[256 + t] = vm4[t];
        } else {
            int u = t - 128;
            s4[128 + u] = qc4[u];
            s4[384 + u] = vc4[u];
        }
    }
    __syncthreads();

    const float cm = __ldg(vbm) + __ldg(rm);
    const float cc = __ldg(vbc) + __ldg(rc);

    int s0 = tile * 32 + w * 4;
    #pragma unroll
    for (int r = 0; r < 4; r++) {
        int s = s0 + r;
        const float* kp = key + (((size_t)b * S_ + s) << 9);
        float kv[16];
        #pragma unroll
        for (int j = 0; j < 16; j++) kv[j] = kp[lane + 32 * j];
        float em = 0.f, ec = 0.f;
        #pragma unroll
        for (int j = 0; j < 16; j++) {
            int idx = lane + 32 * j;
            em += sq[1024 + idx] * tanha(sq[idx] + kv[j]);
            ec += sq[1536 + idx] * tanha(sq[512 + idx] + kv[j]);
        }
        #pragma unroll
        for (int off = 16; off; off >>= 1) {
            em += __shfl_down_sync(0xffffffffu, em, off);
            ec += __shfl_down_sync(0xffffffffu, ec, off);
        }
        if (lane == 0) {
            g_me[b * S_ + s] = em + cm;
            g_ce[b * S_ + s] = ec + cc;
        }
    }
}

// ---------------- K2: fused cutoff + scans + windows -> beta -------
// Product scan runs with omp=1 placeholders for s >= MONO_S_ (exact:
// prefix products before s are unaffected; once ip hits 0 at Z < 384
// it stays 0). Z detected in-kernel; fallback branch recomputes
// energies + redoes the scan if no underflow occurred (rare).
__global__ void __launch_bounds__(1024) k_scan(
        const float* __restrict__ noise, const float* __restrict__ prev,
        const float* __restrict__ key,
        const float* __restrict__ vbm, const float* __restrict__ rm,
        const float* __restrict__ vbc, const float* __restrict__ rc) {
    int b = blockIdx.x, s = threadIdx.x;   // 1024 threads
    int lane = s & 31, wid = s >> 5;
    const int base = b * S_;
    __shared__ float smA[S_];
    __shared__ float smC[S_];
    __shared__ float wa[32], wb[32], wc[32];
    __shared__ int   s_wf[MONO_TILES_];
    __shared__ float s_psum;

    bool head = (s < MONO_S_);
    float e  = head ? g_me[base + s] : 0.f;
    float c  = head ? g_ce[base + s] : 0.f;
    float nz = noise[base + s];
    float pv = prev[base + s];

    float p = 1.f / (1.f + __expf(-(e + nz)));
    float omp = head ? (1.f - p) : 1.f;

    // product scan #1 (+ prev-sum concurrently)
    float x = omp;
    #pragma unroll
    for (int o = 1; o < 32; o <<= 1) {
        float y = __shfl_up_sync(0xffffffffu, x, o);
        if (lane >= o) x *= y;
    }
    if (lane == 31) wa[wid] = x;
    float ts = pv;
    #pragma unroll
    for (int off = 16; off; off >>= 1) ts += __shfl_down_sync(0xffffffffu, ts, off);
    if (lane == 0) wb[wid] = ts;
    __syncthreads();                                        // B1

    if (wid == 0) {
        float a = wa[lane];
        #pragma unroll
        for (int o = 1; o < 32; o <<= 1) {
            float y = __shfl_up_sync(0xffffffffu, a, o);
            if (lane >= o) a *= y;
        }
        wa[lane] = a;
    } else if (wid == 1) {
        float a = wb[lane];
        #pragma unroll
        for (int off = 16; off; off >>= 1) a += __shfl_down_sync(0xffffffffu, a, off);
        if (lane == 0) s_psum = a;
    }
    __syncthreads();                                        // B2

    float ip = wid ? x * wa[wid - 1] : x;
    // cutoff detection piggybacked before B3
    unsigned zb = __ballot_sync(0xffffffffu, ip == 0.f);
    if (wid < MONO_TILES_ && lane == 0)
        s_wf[wid] = zb ? (wid * 32 + __ffs(zb) - 1) : 0x7fffffff;
    smA[s] = ip;
    __syncthreads();                                        // B3

    int Z = 0x7fffffff;
    #pragma unroll
    for (int i = 0; i < MONO_TILES_; i++) Z = min(Z, s_wf[i]);
    const int cut = (Z <= MONO_S_ - 33) ? Z + 32 : 1024;
    if (s == 0) g_cut[b] = cut;

    if (cut >= 1024) {
        // rare fallback: compute tail energies, redo the product scan
        if (!head) {
            const float cm = __ldg(vbm) + __ldg(rm);
            const float cc = __ldg(vbc) + __ldg(rc);
            const float* kp = key + (((size_t)base + s) << 9);
            const float* qm = g_qbm + b * ATT_;
            const float* qc = g_qbc + b * ATT_;
            float em = 0.f, ec = 0.f;
            for (int j = 0; j < ATT_; j++) {
                float kvj = kp[j];
                em += g_vnm[j] * tanha(qm[j] + kvj);
                ec += g_vnc[j] * tanha(qc[j] + kvj);
            }
            e = em + cm;
            c = ec + cc;
            p = 1.f / (1.f + __expf(-(e + nz)));
        }
        if (s == S_ - 1) p = 1.f;
        omp = 1.f - p;
        float x2f = omp;
        #pragma unroll
        for (int o = 1; o < 32; o <<= 1) {
            float y = __shfl_up_sync(0xffffffffu, x2f, o);
            if (lane >= o) x2f *= y;
        }
        if (lane == 31) wa[wid] = x2f;
        __syncthreads();
        if (wid == 0) {
            float a = wa[lane];
            #pragma unroll
            for (int o = 1; o < 32; o <<= 1) {
                float y = __shfl_up_sync(0xffffffffu, a, o);
                if (lane >= o) a *= y;
            }
            wa[lane] = a;
        }
        __syncthreads();
        float ip2 = wid ? x2f * wa[wid - 1] : x2f;
        smA[s] = ip2;
        __syncthreads();
    }

    const bool dead = (s > cut);
    smC[s] = c;

    float cp = s ? smA[s - 1] : 1.f;       // dead lanes: cp == 0 exactly
    float cpc = fminf(fmaxf(cp, 1e-20f), 1.f);
    float y2 = dead ? 0.f : (pv / s_psum) / cpc;

    float xs = y2;
    #pragma unroll
    for (int o = 1; o < 32; o <<= 1) {
        float y = __shfl_up_sync(0xffffffffu, xs, o);
        if (lane >= o) xs += y;
    }
    if (lane == 31) wc[wid] = xs;
    __syncthreads();                                        // B4
    if (wid == 0) {
        float a = wc[lane];
        #pragma unroll
        for (int o = 1; o < 32; o <<= 1) {
            float y = __shfl_up_sync(0xffffffffu, a, o);
            if (lane >= o) a += y;
        }
        wc[lane] = a;
    }
    __syncthreads();                                        // B5
    float cs = wid ? xs + wc[wid - 1] : xs;
    float alpha = p * cp * cs;              // dead -> p*0*cs = 0 exactly

    float mx = c;
    #pragma unroll
    for (int j = 1; j < W_; j++) { int i = s - j; if (i >= 0) mx = fmaxf(mx, smC[i]); }
    float eu = __expf(c - mx);              // <= 1, never inf
    smA[s] = eu;
    __syncthreads();                                        // B6

    float den = 0.f;
    #pragma unroll
    for (int j = 0; j < W_; j++) { int i = s - j; if (i >= 0) den += smA[i]; }
    den = fmaxf(den, 1e-10f);
    float g = dead ? 0.f : alpha / den;
    smC[s] = g;
    __syncthreads();                                        // B7

    float acc = 0.f;
    #pragma unroll
    for (int j = 0; j < W_; j++) { int i = s + j; if (i < S_) acc += smC[i]; }
    g_beta[base + s] = dead ? 0.f : eu * acc;
}

// ---------------- K3: context = beta . value ----------------------
// 24 chunks cover the normal case (cut <= 383); the stride-24 loop is
// pure insurance for the cut==1024 fallback.
#define SCHUNK_ 16
#define NCHUNK_LIVE_ 24
__global__ void __launch_bounds__(256) k_ctx(const float* __restrict__ value,
                                             float* __restrict__ out) {
    int b = blockIdx.y;
    int cut = g_cut[b];
    int t = threadIdx.x;
    __shared__ float sb[SCHUNK_];

    for (int sc = blockIdx.x; sc < S_ / SCHUNK_; sc += NCHUNK_LIVE_) {
        if (sc * SCHUNK_ > cut) return;      // beta exactly 0 beyond cut
        if (t < SCHUNK_) sb[t] = g_beta[b * S_ + sc * SCHUNK_ + t];
        __syncthreads();
        const float* vp = value + (((size_t)b * S_ + sc * SCHUNK_) << 9);
        float a0 = 0.f, a1 = 0.f;
        #pragma unroll
        for (int s = 0; s < SCHUNK_; s++) {
            float bs = sb[s];
            a0 += bs * vp[(s << 9) + t];
            a1 += bs * vp[(s << 9) + t + 256];
        }
        atomicAdd(out + b * 512 + t,       a0);
        atomicAdd(out + b * 512 + t + 256, a1);
        __syncthreads();
    }
}

// ---------------- launch ------------------------------------------
extern "C" void kernel_launch(void* const* d_in, const int* in_sizes, int n_in,
                              void* d_out, int out_size) {
    const float* dec   = (const float*)d_in[0];
    const float* key   = (const float*)d_in[1];
    const float* value = (const float*)d_in[2];
    const float* prev  = (const float*)d_in[3];
    const float* noise = (const float*)d_in[4];
    const float* Wm    = (const float*)d_in[5];
    const float* bm    = (const float*)d_in[6];
    const float* vm    = (const float*)d_in[7];
    const float* gm    = (const float*)d_in[8];
    const float* vbm   = (const float*)d_in[9];
    const float* rm    = (const float*)d_in[10];
    const float* Wc    = (const float*)d_in[11];
    const float* bc    = (const float*)d_in[12];
    const float* vc    = (const float*)d_in[13];
    const float* gc    = (const float*)d_in[14];
    const float* vbc   = (const float*)d_in[15];
    const float* rc    = (const float*)d_in[16];
    float* out = (float*)d_out;

    k_pre<<<dim3(32, 3), 256>>>(dec, Wm, bm, Wc, bc, vm, gm, vc, gc, out);
    k_both<<<dim3(MONO_TILES_, B_), 256>>>(key, vbm, rm, vbc, rc);
    k_scan<<<B_, S_>>>(noise, prev, key, vbm, rm, vbc, rc);
    k_ctx<<<dim3(NCHUNK_LIVE_, B_), 256>>>(value, out);
}